// round 2
// baseline (speedup 1.0000x reference)
#include <cuda_runtime.h>

#define NMAX 100000
#define EMAX 3200000

// ---- device scratch (no allocations allowed) ----
__device__ float g_deg [NMAX];
__device__ float g_dinv[NMAX];
__device__ float g_h1  [NMAX * 16];
__device__ float g_agg1[NMAX * 16];
__device__ float g_r   [NMAX * 16];
__device__ float g_agg2[NMAX * 16];
__device__ float g_norm[EMAX];
__device__ int   g_is64;

__device__ __forceinline__ void red4(float* p, float a, float b, float c, float d) {
    asm volatile("red.global.add.v4.f32 [%0], {%1, %2, %3, %4};"
                 :: "l"(p), "f"(a), "f"(b), "f"(c), "f"(d) : "memory");
}

// Detect whether edge_index is int64 (odd 32-bit words all zero) or int32.
__global__ void detect_kernel(const unsigned int* __restrict__ idx) {
    __shared__ int found;
    if (threadIdx.x == 0) found = 0;
    __syncthreads();
    for (int i = threadIdx.x; i < 2048; i += blockDim.x) {
        if (idx[2 * i + 1] != 0u) found = 1;
    }
    __syncthreads();
    if (threadIdx.x == 0) g_is64 = (found == 0);
}

__global__ void deg_init_kernel(int n) {
    int i = blockIdx.x * blockDim.x + threadIdx.x;
    if (i < n) g_deg[i] = 1.0f;   // self-loop weight
}

__global__ void deg_acc_kernel(const void* __restrict__ idxv, const float* __restrict__ w, int E) {
    int e = blockIdx.x * blockDim.x + threadIdx.x;
    if (e >= E) return;
    int col;
    if (g_is64) col = (int)((const long long*)idxv)[(size_t)E + e];
    else        col = ((const int*)idxv)[E + e];
    atomicAdd(&g_deg[col], w[e]);
}

__global__ void dinv_kernel(int n) {
    int i = blockIdx.x * blockDim.x + threadIdx.x;
    if (i < n) g_dinv[i] = rsqrtf(g_deg[i]);
}

// h1 = x @ W1 ; also initialize agg1 with the self-loop term h1 * dinv^2
__global__ __launch_bounds__(128) void gemm1_kernel(const float* __restrict__ x,
                                                    const float* __restrict__ W1, int n) {
    __shared__ float Ws[256 * 16];
    __shared__ float xs[32][129];
    int t = threadIdx.x;
    for (int i = t; i < 4096; i += 128) Ws[i] = W1[i];
    int node0 = blockIdx.x * 128;
    float acc[16];
#pragma unroll
    for (int o = 0; o < 16; o++) acc[o] = 0.f;

    for (int kk = 0; kk < 256; kk += 32) {
        __syncthreads();
#pragma unroll
        for (int j = 0; j < 32; j++) {
            int i = t + 128 * j;          // 0..4095
            int nloc = i >> 5, k = i & 31;
            int node = node0 + nloc;
            xs[k][nloc] = (node < n) ? x[node * 256 + kk + k] : 0.f;
        }
        __syncthreads();
#pragma unroll
        for (int k = 0; k < 32; k++) {
            float xv = xs[k][t];
            const float4* wr = (const float4*)&Ws[(kk + k) * 16];
            float4 w0 = wr[0], w1 = wr[1], w2 = wr[2], w3 = wr[3];
            acc[0]  += xv * w0.x; acc[1]  += xv * w0.y; acc[2]  += xv * w0.z; acc[3]  += xv * w0.w;
            acc[4]  += xv * w1.x; acc[5]  += xv * w1.y; acc[6]  += xv * w1.z; acc[7]  += xv * w1.w;
            acc[8]  += xv * w2.x; acc[9]  += xv * w2.y; acc[10] += xv * w2.z; acc[11] += xv * w2.w;
            acc[12] += xv * w3.x; acc[13] += xv * w3.y; acc[14] += xv * w3.z; acc[15] += xv * w3.w;
        }
    }
    int node = node0 + t;
    if (node < n) {
        float di = g_dinv[node];
        float s = di * di;
        float4* hp = (float4*)(g_h1 + (size_t)node * 16);
        float4* ap = (float4*)(g_agg1 + (size_t)node * 16);
#pragma unroll
        for (int q = 0; q < 4; q++) {
            float4 v = make_float4(acc[4 * q], acc[4 * q + 1], acc[4 * q + 2], acc[4 * q + 3]);
            hp[q] = v;
            ap[q] = make_float4(v.x * s, v.y * s, v.z * s, v.w * s);
        }
    }
}

// LAYER==1: gather g_h1 -> scatter g_agg1, compute+store norm.
// LAYER==2: gather g_r  -> scatter g_agg2, reuse norm.
template <int LAYER>
__global__ __launch_bounds__(256) void agg_kernel(const void* __restrict__ idxv,
                                                  const float* __restrict__ w, int E) {
    int e = blockIdx.x * blockDim.x + threadIdx.x;
    if (e >= E) return;
    int row, col;
    if (g_is64) {
        const long long* p = (const long long*)idxv;
        row = (int)p[e];
        col = (int)p[(size_t)E + e];
    } else {
        const int* p = (const int*)idxv;
        row = p[e];
        col = p[E + e];
    }
    float norm;
    if (LAYER == 1) {
        norm = g_dinv[row] * w[e] * g_dinv[col];
        g_norm[e] = norm;
    } else {
        norm = g_norm[e];
    }
    const float* hsrc = (LAYER == 1) ? g_h1 : g_r;
    float* odst       = (LAYER == 1) ? g_agg1 : g_agg2;
    const float4* hp = (const float4*)(hsrc + (size_t)row * 16);
    float* op = odst + (size_t)col * 16;
    float4 a;
    a = hp[0]; red4(op + 0,  a.x * norm, a.y * norm, a.z * norm, a.w * norm);
    a = hp[1]; red4(op + 4,  a.x * norm, a.y * norm, a.z * norm, a.w * norm);
    a = hp[2]; red4(op + 8,  a.x * norm, a.y * norm, a.z * norm, a.w * norm);
    a = hp[3]; red4(op + 12, a.x * norm, a.y * norm, a.z * norm, a.w * norm);
}

// r = relu(agg1 + b1); agg2 init = r * dinv^2 (self-loop of layer 2)
__global__ void relu_init_kernel(const float* __restrict__ b1, int n) {
    int i = blockIdx.x * blockDim.x + threadIdx.x;
    if (i >= n) return;
    float di = g_dinv[i];
    float s = di * di;
    const float4* ap = (const float4*)(g_agg1 + (size_t)i * 16);
    float4* rp = (float4*)(g_r + (size_t)i * 16);
    float4* a2 = (float4*)(g_agg2 + (size_t)i * 16);
    const float4* bp = (const float4*)b1;
#pragma unroll
    for (int q = 0; q < 4; q++) {
        float4 v = ap[q], b = bp[q];
        v.x = fmaxf(v.x + b.x, 0.f);
        v.y = fmaxf(v.y + b.y, 0.f);
        v.z = fmaxf(v.z + b.z, 0.f);
        v.w = fmaxf(v.w + b.w, 0.f);
        rp[q] = v;
        a2[q] = make_float4(v.x * s, v.y * s, v.z * s, v.w * s);
    }
}

// out = log_softmax(agg2 @ W2 + b2)
__global__ __launch_bounds__(128) void final_kernel(const float* __restrict__ W2,
                                                    const float* __restrict__ b2,
                                                    float* __restrict__ out, int n) {
    __shared__ float W2s[16 * 40];
    __shared__ float b2s[40];
    int t = threadIdx.x;
    for (int i = t; i < 640; i += 128) W2s[i] = W2[i];
    if (t < 40) b2s[t] = b2[t];
    __syncthreads();
    int node = blockIdx.x * 128 + t;
    if (node >= n) return;

    float h[16];
    const float4* ap = (const float4*)(g_agg2 + (size_t)node * 16);
#pragma unroll
    for (int q = 0; q < 4; q++) {
        float4 v = ap[q];
        h[4 * q] = v.x; h[4 * q + 1] = v.y; h[4 * q + 2] = v.z; h[4 * q + 3] = v.w;
    }
    float acc[40];
#pragma unroll
    for (int o = 0; o < 40; o++) acc[o] = b2s[o];
#pragma unroll
    for (int k = 0; k < 16; k++) {
        float hv = h[k];
        const float4* wr = (const float4*)&W2s[k * 40];
#pragma unroll
        for (int q = 0; q < 10; q++) {
            float4 wv = wr[q];
            acc[4 * q]     += hv * wv.x;
            acc[4 * q + 1] += hv * wv.y;
            acc[4 * q + 2] += hv * wv.z;
            acc[4 * q + 3] += hv * wv.w;
        }
    }
    float m = acc[0];
#pragma unroll
    for (int o = 1; o < 40; o++) m = fmaxf(m, acc[o]);
    float s = 0.f;
#pragma unroll
    for (int o = 0; o < 40; o++) s += __expf(acc[o] - m);
    float l = m + __logf(s);
    float4* op = (float4*)(out + (size_t)node * 40);
#pragma unroll
    for (int q = 0; q < 10; q++) {
        op[q] = make_float4(acc[4 * q] - l, acc[4 * q + 1] - l,
                            acc[4 * q + 2] - l, acc[4 * q + 3] - l);
    }
}

extern "C" void kernel_launch(void* const* d_in, const int* in_sizes, int n_in,
                              void* d_out, int out_size) {
    const float* x  = (const float*)d_in[0];
    const void*  ei = d_in[1];
    const float* ew = (const float*)d_in[2];
    const float* W1 = (const float*)d_in[3];
    const float* b1 = (const float*)d_in[4];
    const float* W2 = (const float*)d_in[5];
    const float* b2 = (const float*)d_in[6];
    float* out = (float*)d_out;

    int n = in_sizes[0] / 256;   // N nodes
    int E = in_sizes[2];         // edges (edge_weight count)

    int nb  = (n + 255) / 256;
    int ebl = (E + 255) / 256;

    detect_kernel<<<1, 256>>>((const unsigned int*)ei);
    deg_init_kernel<<<nb, 256>>>(n);
    deg_acc_kernel<<<ebl, 256>>>(ei, ew, E);
    dinv_kernel<<<nb, 256>>>(n);
    gemm1_kernel<<<(n + 127) / 128, 128>>>(x, W1, n);
    agg_kernel<1><<<ebl, 256>>>(ei, ew, E);
    relu_init_kernel<<<nb, 256>>>(b1, n);
    agg_kernel<2><<<ebl, 256>>>(ei, ew, E);
    final_kernel<<<(n + 127) / 128, 128>>>(W2, b2, out, n);
}

// round 3
// speedup vs baseline: 1.3927x; 1.3927x over previous
#include <cuda_runtime.h>

#define NMAX 100000
#define EMAX 3200000

// ---- device scratch (no allocations allowed) ----
__device__ float g_deg [NMAX];
__device__ float g_dinv[NMAX];
__device__ int   g_cnt [NMAX];
__device__ int   g_off [NMAX];
__device__ int   g_cur [NMAX];
__device__ unsigned long long g_csr[EMAX];   // (norm<<32 | row)
__device__ float g_h1  [NMAX * 16];
__device__ float g_r   [NMAX * 16];
__device__ float g_agg2[NMAX * 16];
__device__ int   g_bsum[1024];
__device__ int   g_is64;

// Detect whether edge_index is int64 (odd 32-bit words all zero) or int32.
__global__ void detect_kernel(const unsigned int* __restrict__ idx) {
    __shared__ int found;
    if (threadIdx.x == 0) found = 0;
    __syncthreads();
    for (int i = threadIdx.x; i < 2048; i += blockDim.x) {
        if (idx[2 * i + 1] != 0u) found = 1;
    }
    __syncthreads();
    if (threadIdx.x == 0) g_is64 = (found == 0);
}

__global__ void init_kernel(int n) {
    int i = blockIdx.x * blockDim.x + threadIdx.x;
    if (i < n) { g_deg[i] = 1.0f; g_cnt[i] = 0; }   // self-loop weight 1
}

// histogram: weighted degree + integer in-degree per destination
__global__ void hist_kernel(const void* __restrict__ idxv, const float* __restrict__ w, int E) {
    int e = blockIdx.x * blockDim.x + threadIdx.x;
    if (e >= E) return;
    int col;
    if (g_is64) col = (int)((const long long*)idxv)[(size_t)E + e];
    else        col = ((const int*)idxv)[E + e];
    atomicAdd(&g_deg[col], w[e]);
    atomicAdd(&g_cnt[col], 1);
}

__global__ void dinv_kernel(int n) {
    int i = blockIdx.x * blockDim.x + threadIdx.x;
    if (i < n) g_dinv[i] = rsqrtf(g_deg[i]);
}

// ---- 3-pass exclusive scan of g_cnt -> g_off (and g_cur copy) ----
__global__ __launch_bounds__(256) void scanA_kernel(int n) {
    __shared__ int s[256];
    int t = threadIdx.x;
    int i = blockIdx.x * 256 + t;
    int v = (i < n) ? g_cnt[i] : 0;
    s[t] = v;
    __syncthreads();
    for (int d = 128; d > 0; d >>= 1) {
        if (t < d) s[t] += s[t + d];
        __syncthreads();
    }
    if (t == 0) g_bsum[blockIdx.x] = s[0];
}

__global__ __launch_bounds__(1024) void scanB_kernel(int nb) {
    __shared__ int s[1024];
    int t = threadIdx.x;
    int v = (t < nb) ? g_bsum[t] : 0;
    s[t] = v;
    __syncthreads();
    for (int d = 1; d < 1024; d <<= 1) {
        int x = (t >= d) ? s[t - d] : 0;
        __syncthreads();
        s[t] += x;
        __syncthreads();
    }
    if (t < nb) g_bsum[t] = s[t] - v;   // exclusive
}

__global__ __launch_bounds__(256) void scanC_kernel(int n) {
    __shared__ int s[256];
    int t = threadIdx.x;
    int i = blockIdx.x * 256 + t;
    int v = (i < n) ? g_cnt[i] : 0;
    s[t] = v;
    __syncthreads();
    for (int d = 1; d < 256; d <<= 1) {
        int x = (t >= d) ? s[t - d] : 0;
        __syncthreads();
        s[t] += x;
        __syncthreads();
    }
    if (i < n) {
        int off = g_bsum[blockIdx.x] + s[t] - v;
        g_off[i] = off;
        g_cur[i] = off;
    }
}

// scatter edges into CSR, computing norm once
__global__ __launch_bounds__(256) void scatter_kernel(const void* __restrict__ idxv,
                                                      const float* __restrict__ w, int E) {
    int e = blockIdx.x * blockDim.x + threadIdx.x;
    if (e >= E) return;
    int row, col;
    if (g_is64) {
        const long long* p = (const long long*)idxv;
        row = (int)p[e];
        col = (int)p[(size_t)E + e];
    } else {
        const int* p = (const int*)idxv;
        row = p[e];
        col = p[E + e];
    }
    float norm = g_dinv[row] * w[e] * g_dinv[col];
    int pos = atomicAdd(&g_cur[col], 1);
    g_csr[pos] = ((unsigned long long)__float_as_uint(norm) << 32) | (unsigned int)row;
}

// h1 = x @ W1
__global__ __launch_bounds__(128) void gemm1_kernel(const float* __restrict__ x,
                                                    const float* __restrict__ W1, int n) {
    __shared__ float Ws[256 * 16];
    __shared__ float xs[32][129];
    int t = threadIdx.x;
    for (int i = t; i < 4096; i += 128) Ws[i] = W1[i];
    int node0 = blockIdx.x * 128;
    float acc[16];
#pragma unroll
    for (int o = 0; o < 16; o++) acc[o] = 0.f;

    for (int kk = 0; kk < 256; kk += 32) {
        __syncthreads();
#pragma unroll
        for (int j = 0; j < 32; j++) {
            int i = t + 128 * j;
            int nloc = i >> 5, k = i & 31;
            int node = node0 + nloc;
            xs[k][nloc] = (node < n) ? x[node * 256 + kk + k] : 0.f;
        }
        __syncthreads();
#pragma unroll
        for (int k = 0; k < 32; k++) {
            float xv = xs[k][t];
            const float4* wr = (const float4*)&Ws[(kk + k) * 16];
            float4 w0 = wr[0], w1 = wr[1], w2 = wr[2], w3 = wr[3];
            acc[0]  += xv * w0.x; acc[1]  += xv * w0.y; acc[2]  += xv * w0.z; acc[3]  += xv * w0.w;
            acc[4]  += xv * w1.x; acc[5]  += xv * w1.y; acc[6]  += xv * w1.z; acc[7]  += xv * w1.w;
            acc[8]  += xv * w2.x; acc[9]  += xv * w2.y; acc[10] += xv * w2.z; acc[11] += xv * w2.w;
            acc[12] += xv * w3.x; acc[13] += xv * w3.y; acc[14] += xv * w3.z; acc[15] += xv * w3.w;
        }
    }
    int node = node0 + t;
    if (node < n) {
        float4* hp = (float4*)(g_h1 + (size_t)node * 16);
#pragma unroll
        for (int q = 0; q < 4; q++)
            hp[q] = make_float4(acc[4 * q], acc[4 * q + 1], acc[4 * q + 2], acc[4 * q + 3]);
    }
}

// Pull-mode aggregation: one warp per node. 8 edge-slots x 4 feature-lanes.
// LAYER==1: src g_h1, dst g_r with bias+ReLU fused.
// LAYER==2: src g_r,  dst g_agg2.
template <int LAYER>
__global__ __launch_bounds__(256) void agg_kernel(const float* __restrict__ b1, int n) {
    int node = (blockIdx.x * blockDim.x + threadIdx.x) >> 5;
    if (node >= n) return;
    int lane = threadIdx.x & 31;
    int es = lane >> 2, f = lane & 3;
    const float* src = (LAYER == 1) ? g_h1 : g_r;

    int start = g_off[node];
    int end   = start + g_cnt[node];
    float4 acc = make_float4(0.f, 0.f, 0.f, 0.f);
    for (int e = start + es; e < end; e += 8) {
        unsigned long long v = g_csr[e];
        int row = (int)(unsigned int)(v & 0xffffffffu);
        float norm = __uint_as_float((unsigned int)(v >> 32));
        float4 h = ((const float4*)(src + (size_t)row * 16))[f];
        acc.x += h.x * norm; acc.y += h.y * norm;
        acc.z += h.z * norm; acc.w += h.w * norm;
    }
#pragma unroll
    for (int s = 16; s >= 4; s >>= 1) {
        acc.x += __shfl_down_sync(0xffffffff, acc.x, s);
        acc.y += __shfl_down_sync(0xffffffff, acc.y, s);
        acc.z += __shfl_down_sync(0xffffffff, acc.z, s);
        acc.w += __shfl_down_sync(0xffffffff, acc.w, s);
    }
    if (es == 0) {
        float di = g_dinv[node];
        float sl = di * di;
        float4 h = ((const float4*)(src + (size_t)node * 16))[f];
        acc.x += h.x * sl; acc.y += h.y * sl;
        acc.z += h.z * sl; acc.w += h.w * sl;
        if (LAYER == 1) {
            float4 b = ((const float4*)b1)[f];
            acc.x = fmaxf(acc.x + b.x, 0.f);
            acc.y = fmaxf(acc.y + b.y, 0.f);
            acc.z = fmaxf(acc.z + b.z, 0.f);
            acc.w = fmaxf(acc.w + b.w, 0.f);
            ((float4*)(g_r + (size_t)node * 16))[f] = acc;
        } else {
            ((float4*)(g_agg2 + (size_t)node * 16))[f] = acc;
        }
    }
}

// out = log_softmax(agg2 @ W2 + b2)
__global__ __launch_bounds__(128) void final_kernel(const float* __restrict__ W2,
                                                    const float* __restrict__ b2,
                                                    float* __restrict__ out, int n) {
    __shared__ float W2s[16 * 40];
    __shared__ float b2s[40];
    int t = threadIdx.x;
    for (int i = t; i < 640; i += 128) W2s[i] = W2[i];
    if (t < 40) b2s[t] = b2[t];
    __syncthreads();
    int node = blockIdx.x * 128 + t;
    if (node >= n) return;

    float h[16];
    const float4* ap = (const float4*)(g_agg2 + (size_t)node * 16);
#pragma unroll
    for (int q = 0; q < 4; q++) {
        float4 v = ap[q];
        h[4 * q] = v.x; h[4 * q + 1] = v.y; h[4 * q + 2] = v.z; h[4 * q + 3] = v.w;
    }
    float acc[40];
#pragma unroll
    for (int o = 0; o < 40; o++) acc[o] = b2s[o];
#pragma unroll
    for (int k = 0; k < 16; k++) {
        float hv = h[k];
        const float4* wr = (const float4*)&W2s[k * 40];
#pragma unroll
        for (int q = 0; q < 10; q++) {
            float4 wv = wr[q];
            acc[4 * q]     += hv * wv.x;
            acc[4 * q + 1] += hv * wv.y;
            acc[4 * q + 2] += hv * wv.z;
            acc[4 * q + 3] += hv * wv.w;
        }
    }
    float m = acc[0];
#pragma unroll
    for (int o = 1; o < 40; o++) m = fmaxf(m, acc[o]);
    float s = 0.f;
#pragma unroll
    for (int o = 0; o < 40; o++) s += __expf(acc[o] - m);
    float l = m + __logf(s);
    float4* op = (float4*)(out + (size_t)node * 40);
#pragma unroll
    for (int q = 0; q < 10; q++) {
        op[q] = make_float4(acc[4 * q] - l, acc[4 * q + 1] - l,
                            acc[4 * q + 2] - l, acc[4 * q + 3] - l);
    }
}

extern "C" void kernel_launch(void* const* d_in, const int* in_sizes, int n_in,
                              void* d_out, int out_size) {
    const float* x  = (const float*)d_in[0];
    const void*  ei = d_in[1];
    const float* ew = (const float*)d_in[2];
    const float* W1 = (const float*)d_in[3];
    const float* b1 = (const float*)d_in[4];
    const float* W2 = (const float*)d_in[5];
    const float* b2 = (const float*)d_in[6];
    float* out = (float*)d_out;

    int n = in_sizes[0] / 256;   // N nodes
    int E = in_sizes[2];         // edges

    int nb  = (n + 255) / 256;   // node blocks (also = #scan blocks)
    int ebl = (E + 255) / 256;

    detect_kernel<<<1, 256>>>((const unsigned int*)ei);
    init_kernel<<<nb, 256>>>(n);
    hist_kernel<<<ebl, 256>>>(ei, ew, E);
    dinv_kernel<<<nb, 256>>>(n);
    scanA_kernel<<<nb, 256>>>(n);
    scanB_kernel<<<1, 1024>>>(nb);
    scanC_kernel<<<nb, 256>>>(n);
    scatter_kernel<<<ebl, 256>>>(ei, ew, E);
    gemm1_kernel<<<(n + 127) / 128, 128>>>(x, W1, n);
    agg_kernel<1><<<(n + 7) / 8, 256>>>(b1, n);
    agg_kernel<2><<<(n + 7) / 8, 256>>>(b1, n);
    final_kernel<<<(n + 127) / 128, 128>>>(W2, b2, out, n);
}